// round 7
// baseline (speedup 1.0000x reference)
#include <cuda_runtime.h>
#include <cuda_fp16.h>

#define BN   4096
#define LEN  60
#define TS   60
#define HD   256
#define ID   6
#define OD   6
#define GD   1024
#define ROWS 32
#define NTH  512
#define KDD  264
#define NCTA (BN / ROWS)
#define AST  36          // float stride of activation buffers [k][row]; 36*4B = 16B-aligned rows
#define ZST  34          // z_s stride (EVEN: float2 stores must be 8B aligned)

typedef unsigned long long u64;

// ---------------- device scratch (allocation-free) ----------------
// Gate-interleaved weights: Wg[k][u*4+g] = W_orig[g*256+u][k]  (g: 0=i,1=f,2=g,3=o)
__device__ __align__(16) float g_Wg_e_ih[8 * GD];      // padded to 8 k-rows (6,7 zero)
__device__ __align__(16) float g_Wg_e_hh[HD * GD];
__device__ __align__(16) float g_bg_e[GD];
__device__ __align__(16) float g_Wg_d_ih[KDD * GD];    // k rows 262..263 zero
__device__ __align__(16) float g_Wg_d_hh[HD * GD];
__device__ __align__(16) float g_bg_d[GD];
__device__ __align__(16) float g_l1T[HD * HD];         // [k][u]
__device__ __align__(16) float g_l2T[HD * OD];         // [u][o]
__device__ __align__(16) float g_attnT[262 * 60];      // [k][l]
__device__ __align__(16) __half g_ench[(size_t)BN * LEN * HD];  // encoder outputs fp16

// ---------------- packed fp32x2 helpers ----------------
__device__ __forceinline__ u64 pack2(float v) {
    u64 r; asm("mov.b64 %0, {%1, %1};" : "=l"(r) : "f"(v)); return r;
}
__device__ __forceinline__ u64 pkf2(float a, float b) {
    u64 r; asm("mov.b64 %0, {%1, %2};" : "=l"(r) : "f"(a), "f"(b)); return r;
}
__device__ __forceinline__ u64 fma2(u64 a, u64 b, u64 c) {
    u64 d; asm("fma.rn.f32x2 %0, %1, %2, %3;" : "=l"(d) : "l"(a), "l"(b), "l"(c)); return d;
}
__device__ __forceinline__ float2 unpk(u64 v) {
    float2 f; asm("mov.b64 {%0, %1}, %2;" : "=f"(f.x), "=f"(f.y) : "l"(v)); return f;
}
__device__ __forceinline__ float sigmf(float x) { return 1.0f / (1.0f + __expf(-x)); }
__device__ __forceinline__ u64 shfl64x1(u64 v) {
    unsigned lo = (unsigned)v, hi = (unsigned)(v >> 32);
    lo = __shfl_xor_sync(~0u, lo, 1);
    hi = __shfl_xor_sync(~0u, hi, 1);
    return ((u64)hi << 32) | lo;
}

__device__ __forceinline__ unsigned su32(const void* p) {
    unsigned a;
    asm("{ .reg .u64 t; cvta.to.shared.u64 t, %1; cvt.u32.u64 %0, t; }" : "=r"(a) : "l"(p));
    return a;
}
__device__ __forceinline__ void cp16(unsigned d, const void* s) {
    asm volatile("cp.async.cg.shared.global [%0], [%1], 16;" :: "r"(d), "l"(s));
}
__device__ __forceinline__ void cpcommit() { asm volatile("cp.async.commit_group;"); }
__device__ __forceinline__ void cpwait1()  { asm volatile("cp.async.wait_group 1;"); }
__device__ __forceinline__ void cpwait0()  { asm volatile("cp.async.wait_group 0;"); }

// per-warp stripe copy: 8 k-rows x 64 cols (2KB) from W row-base (already +64*w)
__device__ __forceinline__ void cp_stripe8(unsigned dst_s, const float* src, int lane) {
    int r2 = lane >> 4, cf = (lane & 15) * 4;
    const float* s = src + r2 * GD + cf;
    unsigned d = dst_s + (unsigned)((r2 * 64 + cf) * 4);
    cp16(d, s);
    cp16(d + 2 * 64 * 4, s + 2 * GD);
    cp16(d + 4 * 64 * 4, s + 4 * GD);
    cp16(d + 6 * 64 * 4, s + 6 * GD);
    cpcommit();
}
// per-warp stripe copy: 16 k-rows x 32 cols (2KB) from l1T row-base (already +32*(w&7))
__device__ __forceinline__ void cp_stripe16(unsigned dst_s, const float* src, int lane) {
    int r4 = lane >> 3, cf = (lane & 7) * 4;
    const float* s = src + r4 * HD + cf;
    unsigned d = dst_s + (unsigned)((r4 * 32 + cf) * 4);
    cp16(d, s);
    cp16(d + 4 * 32 * 4, s + 4 * HD);
    cp16(d + 8 * 32 * 4, s + 8 * HD);
    cp16(d + 12 * 32 * 4, s + 12 * HD);
    cpcommit();
}

// tile: 8 k-rows; thread owns cols (2t,2t+1), all 32 rows (16 row-pair accs)
__device__ __forceinline__ void tile8w(u64 acc[16][2], const float* __restrict__ Ak,
                                       const float* __restrict__ buf, int lane) {
#pragma unroll
    for (int kk = 0; kk < 8; kk++) {
        float2 wv = *(const float2*)&buf[kk * 64 + 2 * lane];
        u64 b0 = pack2(wv.x), b1 = pack2(wv.y);
        const ulonglong2* ap = (const ulonglong2*)(Ak + kk * AST);
#pragma unroll
        for (int i = 0; i < 8; i++) {
            ulonglong2 av = ap[i];
            acc[2 * i][0]     = fma2(av.x, b0, acc[2 * i][0]);
            acc[2 * i][1]     = fma2(av.x, b1, acc[2 * i][1]);
            acc[2 * i + 1][0] = fma2(av.y, b0, acc[2 * i + 1][0]);
            acc[2 * i + 1][1] = fma2(av.y, b1, acc[2 * i + 1][1]);
        }
    }
}

// barrier-free two-segment warp gemm (8-k tiles, per-warp triple-buffered stripes)
__device__ __forceinline__ void gemm_warp(u64 acc[16][2],
        const float* W0, const float* A0, int n0,
        const float* W1, const float* A1, int n1,
        float* swp, unsigned swp_s, int w, int lane) {
    const int NT = n0 + n1;
    const float* ws0 = W0 + 64 * w;
    const float* ws1 = W1 + 64 * w;
    cp_stripe8(swp_s, ws0, lane);
    cp_stripe8(swp_s + 2048, (1 < n0) ? (ws0 + 8 * GD) : (ws1 + (1 - n0) * 8 * GD), lane);
#pragma unroll 1
    for (int j = 0; j < NT; j++) {
        if (j + 1 < NT) cpwait1(); else cpwait0();
        if (j + 2 < NT) {
            int jj = j + 2;
            const float* s = (jj < n0) ? (ws0 + jj * 8 * GD) : (ws1 + (jj - n0) * 8 * GD);
            cp_stripe8(swp_s + (unsigned)((jj % 3) * 2048), s, lane);
        }
        const float* Ak = (j < n0) ? (A0 + j * 8 * AST) : (A1 + (j - n0) * 8 * AST);
        tile8w(acc, Ak, swp + (j % 3) * 512, lane);
    }
}

// l1 tile: 16 k-rows; thread owns 1 col, 16 rows (8 pairs)
__device__ __forceinline__ void tile16_l1(u64 acc[8], const float* __restrict__ Ak,
                                          const float* __restrict__ buf, int lane, int rh) {
#pragma unroll
    for (int kk = 0; kk < 16; kk++) {
        u64 b0 = pack2(buf[kk * 32 + lane]);
        const ulonglong2* ap = (const ulonglong2*)(Ak + kk * AST) + rh * 4;
#pragma unroll
        for (int i = 0; i < 4; i++) {
            ulonglong2 av = ap[i];
            acc[2 * i]     = fma2(av.x, b0, acc[2 * i]);
            acc[2 * i + 1] = fma2(av.y, b0, acc[2 * i + 1]);
        }
    }
}

__device__ __forceinline__ void gemm_warp_l1(u64 acc[8], const float* A0,
        float* swp, unsigned swp_s, int w, int lane, int rh) {
    const int NT = 16;
    const float* ws = g_l1T + 32 * (w & 7);
    cp_stripe16(swp_s, ws, lane);
    cp_stripe16(swp_s + 2048, ws + 16 * HD, lane);
#pragma unroll 1
    for (int j = 0; j < NT; j++) {
        if (j + 1 < NT) cpwait1(); else cpwait0();
        if (j + 2 < NT) cp_stripe16(swp_s + (unsigned)(((j + 2) % 3) * 2048), ws + (j + 2) * 16 * HD, lane);
        tile16_l1(acc, A0 + j * 16 * AST, swp + (j % 3) * 512, lane, rh);
    }
}

// ---------------- prep ----------------
__global__ void prep_kernel(const float* __restrict__ eWih, const float* __restrict__ eWhh,
                            const float* __restrict__ ebih, const float* __restrict__ ebhh,
                            const float* __restrict__ aW,
                            const float* __restrict__ dWih, const float* __restrict__ dWhh,
                            const float* __restrict__ dbih, const float* __restrict__ dbhh,
                            const float* __restrict__ l1W, const float* __restrict__ l2W) {
    int tid = blockIdx.x * blockDim.x + threadIdx.x;
    int stride = gridDim.x * blockDim.x;
    for (int i = tid; i < 8 * GD; i += stride) {
        int k = i / GD, cc = i % GD, u = cc >> 2, g = cc & 3;
        g_Wg_e_ih[i] = (k < ID) ? eWih[(g * HD + u) * ID + k] : 0.0f;
    }
    for (int i = tid; i < HD * GD; i += stride) {
        int k = i / GD, cc = i % GD, u = cc >> 2, g = cc & 3;
        g_Wg_e_hh[i] = eWhh[(g * HD + u) * HD + k];
    }
    for (int i = tid; i < GD; i += stride) {
        int u = i >> 2, g = i & 3;
        g_bg_e[i] = ebih[g * HD + u] + ebhh[g * HD + u];
    }
    for (int i = tid; i < KDD * GD; i += stride) {
        int k = i / GD, cc = i % GD, u = cc >> 2, g = cc & 3;
        g_Wg_d_ih[i] = (k < 262) ? dWih[(g * HD + u) * 262 + k] : 0.0f;
    }
    for (int i = tid; i < HD * GD; i += stride) {
        int k = i / GD, cc = i % GD, u = cc >> 2, g = cc & 3;
        g_Wg_d_hh[i] = dWhh[(g * HD + u) * HD + k];
    }
    for (int i = tid; i < GD; i += stride) {
        int u = i >> 2, g = i & 3;
        g_bg_d[i] = dbih[g * HD + u] + dbhh[g * HD + u];
    }
    for (int i = tid; i < HD * HD; i += stride) { int k = i / HD, u = i % HD; g_l1T[i] = l1W[u * HD + k]; }
    for (int i = tid; i < HD * OD; i += stride) { int k = i / OD, o = i % OD; g_l2T[i] = l2W[o * HD + k]; }
    for (int i = tid; i < 262 * 60; i += stride) {
        int k = i / 60, l = i % 60;
        g_attnT[i] = aW[l * 262 + k];
    }
}

// ---------------- main: one CTA owns 32 batch rows end-to-end ----------------
__global__ void __launch_bounds__(NTH, 1) seq_kernel(const float* __restrict__ x,
                                                     const float* __restrict__ attn_b,
                                                     const float* __restrict__ l1b,
                                                     const float* __restrict__ l2b,
                                                     float* __restrict__ out) {
    extern __shared__ float sm[];
    float* Ah      = sm;                    // [256*36]  h ([k][row])
    float* Ain     = Ah + 256 * AST;        // [264*36]  dec input
    float* Ax      = Ain + 264 * AST;       // [8*36]    enc x (rows 6,7 zero)
    float* stripes = Ax + 8 * AST;          // [16 warps][3][512] per-warp weight stripes
    float* s_s     = stripes + 16 * 3 * 512;// [32][60]  scores
    float* z_s     = s_s + 32 * 60;         // [256][ZST] l1 output [u][r]
    float* l2T_s   = z_s + 256 * ZST;       // [256*6]

    const int t    = threadIdx.x;
    const int lane = t & 31;
    const int w    = t >> 5;
    const int r0   = blockIdx.x * ROWS;
    const int par  = t & 1;                 // 0: epilogue rows 0..15 (+gates i,f), 1: rows 16..31 (+gates g,o)
    const int u    = t >> 1;                // unit
    float* swp = stripes + w * 3 * 512;
    const unsigned swp_s = su32(swp);

    for (int i = t; i < 256 * AST; i += NTH) Ah[i] = 0.0f;
    for (int i = t; i < 8 * AST; i += NTH) Ax[i] = 0.0f;
    if (t < 32) { Ain[262 * AST + t] = 0.0f; Ain[263 * AST + t] = 0.0f; }

    float c[16];
#pragma unroll
    for (int i = 0; i < 16; i++) c[i] = 0.0f;

    float2 bef = *(const float2*)&g_bg_e[2 * t];
    const u64 be0 = pack2(bef.x), be1 = pack2(bef.y);
    float2 bdf = *(const float2*)&g_bg_d[2 * t];
    const u64 bd0 = pack2(bdf.x), bd1 = pack2(bdf.y);
    __syncthreads();

    // ================= encoder =================
    for (int step = 0; step < LEN; step++) {
        if (t < ROWS * ID) {
            int r = t / ID, k = t - r * ID;
            Ax[k * AST + r] = x[(size_t)(r0 + r) * (LEN * ID) + step * ID + k];
        }
        __syncthreads();

        u64 acc[16][2];
#pragma unroll
        for (int i = 0; i < 16; i++) { acc[i][0] = be0; acc[i][1] = be1; }
        gemm_warp(acc, g_Wg_e_ih, Ax, 1, g_Wg_e_hh, Ah, 32, swp, swp_s, w, lane);
        __syncthreads();   // all warps done reading Ah before overwrite

        __half* eb = g_ench + (size_t)r0 * (LEN * HD) + (size_t)step * HD + u;
#pragma unroll
        for (int p = 0; p < 8; p++) {
            u64 s0 = par ? acc[p][0] : acc[8 + p][0];
            u64 s1 = par ? acc[p][1] : acc[8 + p][1];
            u64 x0 = shfl64x1(s0), x1 = shfl64x1(s1);
            float2 gi = unpk(par ? x0 : acc[p][0]);
            float2 gf = unpk(par ? x1 : acc[p][1]);
            float2 gg = unpk(par ? acc[8 + p][0] : x0);
            float2 go = unpk(par ? acc[8 + p][1] : x1);
            float ca = sigmf(gf.x) * c[2 * p]     + sigmf(gi.x) * tanhf(gg.x);
            float cb = sigmf(gf.y) * c[2 * p + 1] + sigmf(gi.y) * tanhf(gg.y);
            float ha = sigmf(go.x) * tanhf(ca);
            float hb = sigmf(go.y) * tanhf(cb);
            c[2 * p] = ca; c[2 * p + 1] = cb;
            int row = par * 16 + 2 * p;
            *(float2*)&Ah[u * AST + row] = make_float2(ha, hb);
            eb[(size_t)row * (LEN * HD)]       = __float2half(ha);
            eb[(size_t)(row + 1) * (LEN * HD)] = __float2half(hb);
        }
        __syncthreads();
    }

    // ================= decoder init =================
#pragma unroll
    for (int i = 0; i < 16; i++) c[i] = 0.0f;
    for (int i = t; i < 256 * 6; i += NTH) l2T_s[i] = g_l2T[i];
    if (t < 32) {
#pragma unroll
        for (int k = 0; k < OD; k++) Ain[k * AST + t] = (k == 4) ? 1.0f : 0.0f;
    }
    const int lA = t & 63, rgp = t >> 6;   // scores: 8 groups of 4 rows
    const u64 abq = pack2((lA < LEN) ? attn_b[lA] : 0.0f);
    const int clv = t & 255, rhv = t >> 8; // l1: 1 col, rows rhv*16..+15
    const u64 l1bq = pack2(l1b[clv]);
    const int rL2 = t / 6, oL2 = t - 6 * (t / 6);
    const float l2bv = (t < ROWS * OD) ? l2b[oL2] : 0.0f;
    __syncthreads();

    // ================= decoder =================
    for (int step = 0; step < TS; step++) {
        // ---- scores: s[r][l] = [h | tok] . attnT[:, l] + b[l]  (attnT from L2)
        if (lA < LEN) {
            u64 sc0 = abq, sc1 = abq;
#pragma unroll 8
            for (int k = 0; k < HD; k++) {
                u64 wv = pack2(__ldg(&g_attnT[k * 60 + lA]));
                const u64* ap = (const u64*)(Ah + k * AST) + rgp * 2;
                sc0 = fma2(ap[0], wv, sc0); sc1 = fma2(ap[1], wv, sc1);
            }
#pragma unroll
            for (int k = 0; k < OD; k++) {
                u64 wv = pack2(__ldg(&g_attnT[(HD + k) * 60 + lA]));
                const u64* ap = (const u64*)(Ain + k * AST) + rgp * 2;
                sc0 = fma2(ap[0], wv, sc0); sc1 = fma2(ap[1], wv, sc1);
            }
            float2 f0 = unpk(sc0), f1 = unpk(sc1);
            int rb = rgp * 4;
            s_s[(rb + 0) * 60 + lA] = f0.x; s_s[(rb + 1) * 60 + lA] = f0.y;
            s_s[(rb + 2) * 60 + lA] = f1.x; s_s[(rb + 3) * 60 + lA] = f1.y;
        }
        __syncthreads();
        // ---- softmax: warp wi handles rows 2wi, 2wi+1
        {
#pragma unroll
            for (int rr = 2 * w; rr < 2 * w + 2; rr++) {
                float* sp = &s_s[rr * 60];
                float v0 = sp[lane];
                float v1 = (lane + 32 < LEN) ? sp[lane + 32] : -1e30f;
                float m = fmaxf(v0, v1);
#pragma unroll
                for (int d = 16; d > 0; d >>= 1) m = fmaxf(m, __shfl_xor_sync(~0u, m, d));
                float e0 = __expf(v0 - m);
                float e1 = (lane + 32 < LEN) ? __expf(v1 - m) : 0.0f;
                float ss = e0 + e1;
#pragma unroll
                for (int d = 16; d > 0; d >>= 1) ss += __shfl_xor_sync(~0u, ss, d);
                float inv = 1.0f / ss;
                sp[lane] = e0 * inv;
                if (lane + 32 < LEN) sp[lane + 32] = e1 * inv;
            }
        }
        __syncthreads();
        // ---- ctx: thread (r = t>>4, 16 h-cols fp16) -> Ain rows 6..261
        {
            int r = t >> 4, c16 = t & 15;
            u64 a8[8];
#pragma unroll
            for (int j = 0; j < 8; j++) a8[j] = 0ULL;
            const __half* ep = g_ench + (size_t)(r0 + r) * (LEN * HD) + c16 * 16;
            const float* apw = &s_s[r * 60];
#pragma unroll 4
            for (int l = 0; l < LEN; l++) {
                u64 aw = pack2(apw[l]);
                const uint4* e4 = (const uint4*)(ep + (size_t)l * HD);
                uint4 v0 = e4[0], v1 = e4[1];
                const unsigned* vv = &v0.x;
#pragma unroll
                for (int j = 0; j < 4; j++) {
                    float2 f = __half22float2(*(const __half2*)&vv[j]);
                    a8[j] = fma2(aw, pkf2(f.x, f.y), a8[j]);
                }
                const unsigned* ww = &v1.x;
#pragma unroll
                for (int j = 0; j < 4; j++) {
                    float2 f = __half22float2(*(const __half2*)&ww[j]);
                    a8[4 + j] = fma2(aw, pkf2(f.x, f.y), a8[4 + j]);
                }
            }
            int kb = 6 + c16 * 16;
#pragma unroll
            for (int j = 0; j < 8; j++) {
                float2 f = unpk(a8[j]);
                Ain[(kb + 2 * j) * AST + r]     = f.x;
                Ain[(kb + 2 * j + 1) * AST + r] = f.y;
            }
        }
        __syncthreads();

        // ---- decoder gates (barrier-free warp gemm: ih K=264 + hh K=256)
        u64 acc[16][2];
#pragma unroll
        for (int i = 0; i < 16; i++) { acc[i][0] = bd0; acc[i][1] = bd1; }
        gemm_warp(acc, g_Wg_d_ih, Ain, 33, g_Wg_d_hh, Ah, 32, swp, swp_s, w, lane);
        __syncthreads();
#pragma unroll
        for (int p = 0; p < 8; p++) {
            u64 s0 = par ? acc[p][0] : acc[8 + p][0];
            u64 s1 = par ? acc[p][1] : acc[8 + p][1];
            u64 x0 = shfl64x1(s0), x1 = shfl64x1(s1);
            float2 gi = unpk(par ? x0 : acc[p][0]);
            float2 gf = unpk(par ? x1 : acc[p][1]);
            float2 gg = unpk(par ? acc[8 + p][0] : x0);
            float2 go = unpk(par ? acc[8 + p][1] : x1);
            float ca = sigmf(gf.x) * c[2 * p]     + sigmf(gi.x) * tanhf(gg.x);
            float cb = sigmf(gf.y) * c[2 * p + 1] + sigmf(gi.y) * tanhf(gg.y);
            float ha = sigmf(go.x) * tanhf(ca);
            float hb = sigmf(go.y) * tanhf(cb);
            c[2 * p] = ca; c[2 * p + 1] = cb;
            *(float2*)&Ah[u * AST + par * 16 + 2 * p] = make_float2(ha, hb);
        }
        __syncthreads();

        // ---- l1 (barrier-free warp gemm): z = relu(h @ l1T + b1)
        {
            u64 a8[8];
#pragma unroll
            for (int i = 0; i < 8; i++) a8[i] = l1bq;
            gemm_warp_l1(a8, Ah, swp, swp_s, w, lane, rhv);
#pragma unroll
            for (int i = 0; i < 8; i++) {
                float2 f = unpk(a8[i]);
                *(float2*)&z_s[clv * ZST + rhv * 16 + 2 * i] =
                    make_float2(fmaxf(f.x, 0.0f), fmaxf(f.y, 0.0f));
            }
        }
        __syncthreads();

        // ---- l2 + output + token feedback
        if (t < ROWS * OD) {
            float s = l2bv;
#pragma unroll 8
            for (int uu = 0; uu < HD; uu++) s += z_s[uu * ZST + rL2] * l2T_s[uu * 6 + oL2];
            out[(size_t)(r0 + rL2) * (TS * OD) + step * OD + oL2] = s;
            Ain[oL2 * AST + rL2] = s;
        }
        __syncthreads();
    }
}

extern "C" void kernel_launch(void* const* d_in, const int* in_sizes, int n_in,
                              void* d_out, int out_size) {
    const float* x    = (const float*)d_in[0];
    const float* eWih = (const float*)d_in[2];
    const float* eWhh = (const float*)d_in[3];
    const float* ebih = (const float*)d_in[4];
    const float* ebhh = (const float*)d_in[5];
    const float* aW   = (const float*)d_in[6];
    const float* ab   = (const float*)d_in[7];
    const float* dWih = (const float*)d_in[8];
    const float* dWhh = (const float*)d_in[9];
    const float* dbih = (const float*)d_in[10];
    const float* dbhh = (const float*)d_in[11];
    const float* l1W  = (const float*)d_in[12];
    const float* l1b  = (const float*)d_in[13];
    const float* l2W  = (const float*)d_in[14];
    const float* l2b  = (const float*)d_in[15];
    float* out = (float*)d_out;

    prep_kernel<<<256, 256>>>(eWih, eWhh, ebih, ebhh, aW, dWih, dWhh, dbih, dbhh, l1W, l2W);

    const int smem_floats = 256 * AST + 264 * AST + 8 * AST + 16 * 3 * 512
                          + 32 * 60 + 256 * ZST + 256 * 6;
    const int smem_bytes = smem_floats * (int)sizeof(float);   // ~223 KB
    cudaFuncSetAttribute(seq_kernel, cudaFuncAttributeMaxDynamicSharedMemorySize, smem_bytes);
    seq_kernel<<<NCTA, NTH, smem_bytes>>>(x, ab, l1b, l2b, out);
}

// round 9
// speedup vs baseline: 1.3496x; 1.3496x over previous
#include <cuda_runtime.h>
#include <cuda_fp16.h>

#define BN   4096
#define LEN  60
#define TS   60
#define HD   256
#define ID   6
#define OD   6
#define GD   1024
#define ROWS 32
#define NTH  512
#define KDD  264
#define NCTA (BN / ROWS)
#define AST  36          // float stride of activation buffers [k][row]

typedef unsigned long long u64;

// ---------------- device scratch (allocation-free) ----------------
// Gate-interleaved weights: Wg[k][u*4+g] = W_orig[g*256+u][k]  (g: 0=i,1=f,2=g,3=o)
__device__ __align__(16) float g_Wg_e_ih[8 * GD];      // padded to 8 k-rows (6,7 zero)
__device__ __align__(16) float g_Wg_e_hh[HD * GD];
__device__ __align__(16) float g_bg_e[GD];
__device__ __align__(16) float g_Wg_d_ih[KDD * GD];    // k rows 262..263 zero
__device__ __align__(16) float g_Wg_d_hh[HD * GD];
__device__ __align__(16) float g_bg_d[GD];
__device__ __align__(16) float g_l1T[HD * HD];         // [k][u]
__device__ __align__(16) float g_l2T[HD * OD];         // [u][o]
__device__ __align__(16) float g_attnT[262 * 60];      // [k][l]
__device__ __align__(16) __half g_ench[(size_t)BN * LEN * HD];  // encoder outputs fp16

// ---------------- packed fp32x2 helpers ----------------
__device__ __forceinline__ u64 pack2(float v) {
    u64 r; asm("mov.b64 %0, {%1, %1};" : "=l"(r) : "f"(v)); return r;
}
__device__ __forceinline__ u64 pkf2(float a, float b) {
    u64 r; asm("mov.b64 %0, {%1, %2};" : "=l"(r) : "f"(a), "f"(b)); return r;
}
__device__ __forceinline__ u64 fma2(u64 a, u64 b, u64 c) {
    u64 d; asm("fma.rn.f32x2 %0, %1, %2, %3;" : "=l"(d) : "l"(a), "l"(b), "l"(c)); return d;
}
__device__ __forceinline__ float2 unpk(u64 v) {
    float2 f; asm("mov.b64 {%0, %1}, %2;" : "=f"(f.x), "=f"(f.y) : "l"(v)); return f;
}
__device__ __forceinline__ float sigmf(float x) { return 1.0f / (1.0f + __expf(-x)); }

__device__ __forceinline__ unsigned su32(const void* p) {
    unsigned a;
    asm("{ .reg .u64 t; cvta.to.shared.u64 t, %1; cvt.u32.u64 %0, t; }" : "=r"(a) : "l"(p));
    return a;
}
__device__ __forceinline__ void cp16(unsigned d, const void* s) {
    asm volatile("cp.async.cg.shared.global [%0], [%1], 16;" :: "r"(d), "l"(s));
}
__device__ __forceinline__ void cpcommit() { asm volatile("cp.async.commit_group;"); }
__device__ __forceinline__ void cpwait1()  { asm volatile("cp.async.wait_group 1;"); }
__device__ __forceinline__ void cpwait0()  { asm volatile("cp.async.wait_group 0;"); }

// copy one 32KB tile (8192 floats): each of 512 threads moves 64B
__device__ __forceinline__ void cp_tile(unsigned dst_s, const float* src, int t) {
    unsigned d = dst_s + (unsigned)(t * 64);
    const char* s = (const char*)src + t * 64;
    cp16(d, s); cp16(d + 16, s + 16); cp16(d + 32, s + 32); cp16(d + 48, s + 48);
    cpcommit();
}

// main-gemm tile: 8 k-rows; thread owns unit u (cols 4u..4u+3), rows half*16..half*16+15.
__device__ __forceinline__ void tile8(u64 acc[8][4], const float* __restrict__ Ak,
                                      const float* __restrict__ buf, int u, int half) {
#pragma unroll
    for (int kk = 0; kk < 8; kk++) {
        float4 w = *(const float4*)&buf[kk * GD + 4 * u];
        u64 b0 = pack2(w.x), b1 = pack2(w.y), b2 = pack2(w.z), b3 = pack2(w.w);
        const u64* ap = (const u64*)(Ak + kk * AST) + half * 8;
#pragma unroll
        for (int i = 0; i < 8; i++) {
            u64 av = ap[i];
            acc[i][0] = fma2(av, b0, acc[i][0]);
            acc[i][1] = fma2(av, b1, acc[i][1]);
            acc[i][2] = fma2(av, b2, acc[i][2]);
            acc[i][3] = fma2(av, b3, acc[i][3]);
        }
    }
}

// two-segment pipelined gemm (tiles of 8 k-rows x 1024 cols, triple-buffered)
__device__ __forceinline__ void gemm_pipe(u64 acc[8][4],
        const float* W0, const float* A0, int n0,
        const float* W1, const float* A1, int n1,
        float* wbuf, unsigned wbuf_s, int t, int u, int half) {
    const int NT = n0 + n1;
    cp_tile(wbuf_s, W0, t);
    {
        const float* w1 = (1 < n0) ? (W0 + 8192) : (W1 + (1 - n0) * 8192);
        cp_tile(wbuf_s + 32768, w1, t);
    }
#pragma unroll 1
    for (int j = 0; j < NT; j++) {
        if (j + 1 < NT) cpwait1(); else cpwait0();
        __syncthreads();
        if (j + 2 < NT) {
            int jj = j + 2;
            const float* ws = (jj < n0) ? (W0 + jj * 8192) : (W1 + (jj - n0) * 8192);
            cp_tile(wbuf_s + (unsigned)((jj % 3) * 32768), ws, t);
        }
        const float* Ak = (j < n0) ? (A0 + j * 8 * AST) : (A1 + (j - n0) * 8 * AST);
        tile8(acc, Ak, wbuf + (j % 3) * 8192, u, half);
    }
}

// l1 tile: 32 k-rows x 256 cols; thread (c2 = cols 2c2,2c2+1; rh -> rows rh*8..rh*8+7)
__device__ __forceinline__ void tile32_l1(u64 acc[4][2], const float* __restrict__ Ak,
                                          const float* __restrict__ buf, int c2, int rh) {
#pragma unroll 8
    for (int kk = 0; kk < 32; kk++) {
        float2 w = *(const float2*)&buf[kk * 256 + 2 * c2];
        u64 b0 = pack2(w.x), b1 = pack2(w.y);
        const u64* ap = (const u64*)(Ak + kk * AST) + rh * 4;
#pragma unroll
        for (int i = 0; i < 4; i++) {
            u64 av = ap[i];
            acc[i][0] = fma2(av, b0, acc[i][0]);
            acc[i][1] = fma2(av, b1, acc[i][1]);
        }
    }
}

__device__ __forceinline__ void gemm_pipe_l1(u64 acc[4][2], const float* W0, const float* A0,
                                             float* wbuf, unsigned wbuf_s, int c2, int rh, int t) {
    const int NT = 8;
    cp_tile(wbuf_s, W0, t);
    cp_tile(wbuf_s + 32768, W0 + 8192, t);
#pragma unroll 1
    for (int j = 0; j < NT; j++) {
        if (j + 1 < NT) cpwait1(); else cpwait0();
        __syncthreads();
        if (j + 2 < NT) cp_tile(wbuf_s + (unsigned)(((j + 2) % 3) * 32768), W0 + (j + 2) * 8192, t);
        tile32_l1(acc, A0 + j * 32 * AST, wbuf + (j % 3) * 8192, c2, rh);
    }
}

// ---------------- prep ----------------
__global__ void prep_kernel(const float* __restrict__ eWih, const float* __restrict__ eWhh,
                            const float* __restrict__ ebih, const float* __restrict__ ebhh,
                            const float* __restrict__ aW,
                            const float* __restrict__ dWih, const float* __restrict__ dWhh,
                            const float* __restrict__ dbih, const float* __restrict__ dbhh,
                            const float* __restrict__ l1W, const float* __restrict__ l2W) {
    int tid = blockIdx.x * blockDim.x + threadIdx.x;
    int stride = gridDim.x * blockDim.x;
    for (int i = tid; i < 8 * GD; i += stride) {
        int k = i / GD, cc = i % GD, u = cc >> 2, g = cc & 3;
        g_Wg_e_ih[i] = (k < ID) ? eWih[(g * HD + u) * ID + k] : 0.0f;
    }
    for (int i = tid; i < HD * GD; i += stride) {
        int k = i / GD, cc = i % GD, u = cc >> 2, g = cc & 3;
        g_Wg_e_hh[i] = eWhh[(g * HD + u) * HD + k];
    }
    for (int i = tid; i < GD; i += stride) {
        int u = i >> 2, g = i & 3;
        g_bg_e[i] = ebih[g * HD + u] + ebhh[g * HD + u];
    }
    for (int i = tid; i < KDD * GD; i += stride) {
        int k = i / GD, cc = i % GD, u = cc >> 2, g = cc & 3;
        g_Wg_d_ih[i] = (k < 262) ? dWih[(g * HD + u) * 262 + k] : 0.0f;
    }
    for (int i = tid; i < HD * GD; i += stride) {
        int k = i / GD, cc = i % GD, u = cc >> 2, g = cc & 3;
        g_Wg_d_hh[i] = dWhh[(g * HD + u) * HD + k];
    }
    for (int i = tid; i < GD; i += stride) {
        int u = i >> 2, g = i & 3;
        g_bg_d[i] = dbih[g * HD + u] + dbhh[g * HD + u];
    }
    for (int i = tid; i < HD * HD; i += stride) { int k = i / HD, u = i % HD; g_l1T[i] = l1W[u * HD + k]; }
    for (int i = tid; i < HD * OD; i += stride) { int k = i / OD, o = i % OD; g_l2T[i] = l2W[o * HD + k]; }
    for (int i = tid; i < 262 * 60; i += stride) {
        int k = i / 60, l = i % 60;
        g_attnT[i] = aW[l * 262 + k];
    }
}

// ---------------- main: one CTA owns 32 batch rows end-to-end ----------------
__global__ void __launch_bounds__(NTH, 1) seq_kernel(const float* __restrict__ x,
                                                     const float* __restrict__ attn_b,
                                                     const float* __restrict__ l1b,
                                                     const float* __restrict__ l2b,
                                                     float* __restrict__ out) {
    extern __shared__ float sm[];
    float* Ah    = sm;                    // [256*36]  h (plain f32, [k][row])
    float* Ain   = Ah + 256 * AST;        // [264*36]  dec input
    float* Ax    = Ain + 264 * AST;       // [8*36]    enc x (rows 6,7 zero)
    float* wbuf  = Ax + 8 * AST;          // [3*8192]  cp.async weight tiles
    float* s_s   = wbuf + 3 * 8192;       // [32*60]   scores
    float* z_s   = s_s + 32 * 60;         // [256*33]  l1 output [u][r]
    float* l2T_s = z_s + 256 * 33;        // [256*6]
    float* be_s  = l2T_s + 256 * 6;       // [1024]
    float* bd_s  = be_s + GD;             // [1024]

    const int t    = threadIdx.x;
    const int r0   = blockIdx.x * ROWS;
    const int u    = t & 255;             // unit (gate cols 4u..4u+3)
    const int half = t >> 8;              // row half: rows half*16 .. half*16+15
    const unsigned wbuf_s = su32(wbuf);

    for (int i = t; i < 256 * AST; i += NTH) Ah[i] = 0.0f;
    for (int i = t; i < 8 * AST; i += NTH) Ax[i] = 0.0f;
    for (int i = t; i < GD; i += NTH) { be_s[i] = g_bg_e[i]; bd_s[i] = g_bg_d[i]; }
    if (t < 32) { Ain[262 * AST + t] = 0.0f; Ain[263 * AST + t] = 0.0f; }

    float c[16];
#pragma unroll
    for (int i = 0; i < 16; i++) c[i] = 0.0f;
    __syncthreads();

    // ================= encoder =================
    for (int step = 0; step < LEN; step++) {
        if (t < ROWS * ID) {
            int r = t / ID, k = t - r * ID;
            Ax[k * AST + r] = x[(size_t)(r0 + r) * (LEN * ID) + step * ID + k];
        }
        u64 acc[8][4];
        {
            float4 bv = *(const float4*)&be_s[4 * u];
            u64 q0 = pack2(bv.x), q1 = pack2(bv.y), q2 = pack2(bv.z), q3 = pack2(bv.w);
#pragma unroll
            for (int i = 0; i < 8; i++) { acc[i][0] = q0; acc[i][1] = q1; acc[i][2] = q2; acc[i][3] = q3; }
        }
        gemm_pipe(acc, g_Wg_e_ih, Ax, 1, g_Wg_e_hh, Ah, 32, wbuf, wbuf_s, t, u, half);
        __syncthreads();   // all tile computes read Ah before overwrite

        __half* eb = g_ench + (size_t)r0 * (LEN * HD) + (size_t)step * HD + u;
#pragma unroll
        for (int i = 0; i < 8; i++) {
            float2 gi = unpk(acc[i][0]), gf = unpk(acc[i][1]);
            float2 gg = unpk(acc[i][2]), go = unpk(acc[i][3]);
            float ca = sigmf(gf.x) * c[2 * i]     + sigmf(gi.x) * tanhf(gg.x);
            float cb = sigmf(gf.y) * c[2 * i + 1] + sigmf(gi.y) * tanhf(gg.y);
            float ha = sigmf(go.x) * tanhf(ca);
            float hb = sigmf(go.y) * tanhf(cb);
            c[2 * i] = ca; c[2 * i + 1] = cb;
            int rr = half * 16 + 2 * i;
            *(float2*)&Ah[u * AST + rr] = make_float2(ha, hb);
            eb[(size_t)rr * (LEN * HD)]       = __float2half(ha);
            eb[(size_t)(rr + 1) * (LEN * HD)] = __float2half(hb);
        }
        __syncthreads();
    }

    // ================= decoder init =================
#pragma unroll
    for (int i = 0; i < 16; i++) c[i] = 0.0f;
    for (int i = t; i < 256 * 6; i += NTH) l2T_s[i] = g_l2T[i];
    if (t < 32) {
#pragma unroll
        for (int k = 0; k < OD; k++) Ain[k * AST + t] = (k == 4) ? 1.0f : 0.0f;
    }
    const int lA = t & 63, rgp = t >> 6;   // scores: 8 groups of 4 rows
    const u64 abq = pack2((lA < LEN) ? attn_b[lA] : 0.0f);
    const int c2v = t & 127, rhv = t >> 7; // l1: 2 cols, 4 row-pair groups
    const u64 l1bq0 = pack2(l1b[2 * c2v]), l1bq1 = pack2(l1b[2 * c2v + 1]);
    const int rL2 = t / 6, oL2 = t - 6 * (t / 6);
    const float l2bv = (t < ROWS * OD) ? l2b[oL2] : 0.0f;
    __syncthreads();

    // ================= decoder =================
    for (int step = 0; step < TS; step++) {
        // ---- scores: s[r][l] = [h | tok] . attnT[:, l] + b[l]  (attnT from L2)
        if (lA < LEN) {
            u64 sc0 = abq, sc1 = abq;
#pragma unroll 8
            for (int k = 0; k < HD; k++) {
                u64 w = pack2(__ldg(&g_attnT[k * 60 + lA]));
                const u64* ap = (const u64*)(Ah + k * AST) + rgp * 2;
                sc0 = fma2(ap[0], w, sc0); sc1 = fma2(ap[1], w, sc1);
            }
#pragma unroll
            for (int k = 0; k < OD; k++) {
                u64 w = pack2(__ldg(&g_attnT[(HD + k) * 60 + lA]));
                const u64* ap = (const u64*)(Ain + k * AST) + rgp * 2;
                sc0 = fma2(ap[0], w, sc0); sc1 = fma2(ap[1], w, sc1);
            }
            float2 f0 = unpk(sc0), f1 = unpk(sc1);
            int rb = rgp * 4;
            s_s[(rb + 0) * 60 + lA] = f0.x; s_s[(rb + 1) * 60 + lA] = f0.y;
            s_s[(rb + 2) * 60 + lA] = f1.x; s_s[(rb + 3) * 60 + lA] = f1.y;
        }
        __syncthreads();
        // ---- softmax: warp w handles rows 2w, 2w+1 (lane i: elems i, i+32)
        {
            int w = t >> 5, lane = t & 31;
#pragma unroll
            for (int rr = 2 * w; rr < 2 * w + 2; rr++) {
                float* sp = &s_s[rr * 60];
                float v0 = sp[lane];
                float v1 = (lane + 32 < LEN) ? sp[lane + 32] : -1e30f;
                float m = fmaxf(v0, v1);
#pragma unroll
                for (int d = 16; d > 0; d >>= 1) m = fmaxf(m, __shfl_xor_sync(~0u, m, d));
                float e0 = __expf(v0 - m);
                float e1 = (lane + 32 < LEN) ? __expf(v1 - m) : 0.0f;
                float ss = e0 + e1;
#pragma unroll
                for (int d = 16; d > 0; d >>= 1) ss += __shfl_xor_sync(~0u, ss, d);
                float inv = 1.0f / ss;
                sp[lane] = e0 * inv;
                if (lane + 32 < LEN) sp[lane + 32] = e1 * inv;
            }
        }
        __syncthreads();
        // ---- ctx: thread (r = t>>4, 16 h-cols fp16) -> Ain rows 6..261
        {
            int r = t >> 4, c16 = t & 15;
            u64 a8[8];
#pragma unroll
            for (int j = 0; j < 8; j++) a8[j] = 0ULL;
            const __half* ep = g_ench + (size_t)(r0 + r) * (LEN * HD) + c16 * 16;
            const float* apw = &s_s[r * 60];
#pragma unroll 4
            for (int l = 0; l < LEN; l++) {
                u64 aw = pack2(apw[l]);
                const uint4* e4 = (const uint4*)(ep + (size_t)l * HD);
                uint4 v0 = e4[0], v1 = e4[1];
                const unsigned* vv = &v0.x;
#pragma unroll
                for (int j = 0; j < 4; j++) {
                    float2 f = __half22float2(*(const __half2*)&vv[j]);
                    a8[j] = fma2(aw, pkf2(f.x, f.y), a8[j]);
                }
                const unsigned* ww = &v1.x;
#pragma unroll
                for (int j = 0; j < 4; j++) {
                    float2 f = __half22float2(*(const __half2*)&ww[j]);
                    a8[4 + j] = fma2(aw, pkf2(f.x, f.y), a8[4 + j]);
                }
            }
            int kb = 6 + c16 * 16;
#pragma unroll
            for (int j = 0; j < 8; j++) {
                float2 f = unpk(a8[j]);
                Ain[(kb + 2 * j) * AST + r]     = f.x;
                Ain[(kb + 2 * j + 1) * AST + r] = f.y;
            }
        }
        __syncthreads();

        // ---- decoder gates (pipelined ih K=264 + hh K=256)
        u64 acc[8][4];
        {
            float4 bv = *(const float4*)&bd_s[4 * u];
            u64 q0 = pack2(bv.x), q1 = pack2(bv.y), q2 = pack2(bv.z), q3 = pack2(bv.w);
#pragma unroll
            for (int i = 0; i < 8; i++) { acc[i][0] = q0; acc[i][1] = q1; acc[i][2] = q2; acc[i][3] = q3; }
        }
        gemm_pipe(acc, g_Wg_d_ih, Ain, 33, g_Wg_d_hh, Ah, 32, wbuf, wbuf_s, t, u, half);
        __syncthreads();
#pragma unroll
        for (int i = 0; i < 8; i++) {
            float2 gi = unpk(acc[i][0]), gf = unpk(acc[i][1]);
            float2 gg = unpk(acc[i][2]), go = unpk(acc[i][3]);
            float ca = sigmf(gf.x) * c[2 * i]     + sigmf(gi.x) * tanhf(gg.x);
            float cb = sigmf(gf.y) * c[2 * i + 1] + sigmf(gi.y) * tanhf(gg.y);
            float ha = sigmf(go.x) * tanhf(ca);
            float hb = sigmf(go.y) * tanhf(cb);
            c[2 * i] = ca; c[2 * i + 1] = cb;
            *(float2*)&Ah[u * AST + half * 16 + 2 * i] = make_float2(ha, hb);
        }
        __syncthreads();

        // ---- l1 (pipelined): z = relu(h @ l1T + b1)
        {
            u64 a4[4][2];
#pragma unroll
            for (int i = 0; i < 4; i++) { a4[i][0] = l1bq0; a4[i][1] = l1bq1; }
            gemm_pipe_l1(a4, g_l1T, Ah, wbuf, wbuf_s, c2v, rhv, t);
#pragma unroll
            for (int i = 0; i < 4; i++) {
                float2 f0 = unpk(a4[i][0]), f1 = unpk(a4[i][1]);
                int rr = rhv * 8 + 2 * i;
                z_s[(2 * c2v) * 33 + rr]     = fmaxf(f0.x, 0.0f);
                z_s[(2 * c2v) * 33 + rr + 1] = fmaxf(f0.y, 0.0f);
                z_s[(2 * c2v + 1) * 33 + rr]     = fmaxf(f1.x, 0.0f);
                z_s[(2 * c2v + 1) * 33 + rr + 1] = fmaxf(f1.y, 0.0f);
            }
        }
        __syncthreads();

        // ---- l2 + output + token feedback
        if (t < ROWS * OD) {
            float s = l2bv;
#pragma unroll 8
            for (int uu = 0; uu < HD; uu++) s += z_s[uu * 33 + rL2] * l2T_s[uu * 6 + oL2];
            out[(size_t)(r0 + rL2) * (TS * OD) + step * OD + oL2] = s;
            Ain[oL2 * AST + rL2] = s;
        }
        __syncthreads();
    }
}

extern "C" void kernel_launch(void* const* d_in, const int* in_sizes, int n_in,
                              void* d_out, int out_size) {
    const float* x    = (const float*)d_in[0];
    const float* eWih = (const float*)d_in[2];
    const float* eWhh = (const float*)d_in[3];
    const float* ebih = (const float*)d_in[4];
    const float* ebhh = (const float*)d_in[5];
    const float* aW   = (const float*)d_in[6];
    const float* ab   = (const float*)d_in[7];
    const float* dWih = (const float*)d_in[8];
    const float* dWhh = (const float*)d_in[9];
    const float* dbih = (const float*)d_in[10];
    const float* dbhh = (const float*)d_in[11];
    const float* l1W  = (const float*)d_in[12];
    const float* l1b  = (const float*)d_in[13];
    const float* l2W  = (const float*)d_in[14];
    const float* l2b  = (const float*)d_in[15];
    float* out = (float*)d_out;

    prep_kernel<<<256, 256>>>(eWih, eWhh, ebih, ebhh, aW, dWih, dWhh, dbih, dbhh, l1W, l2W);

    const int smem_floats = 256 * AST + 264 * AST + 8 * AST + 3 * 8192
                          + 32 * 60 + 256 * 33 + 256 * 6 + 2 * GD;
    const int smem_bytes = smem_floats * (int)sizeof(float);
    cudaFuncSetAttribute(seq_kernel, cudaFuncAttributeMaxDynamicSharedMemorySize, smem_bytes);
    seq_kernel<<<NCTA, NTH, smem_bytes>>>(x, ab, l1b, l2b, out);
}

// round 12
// speedup vs baseline: 1.4923x; 1.1057x over previous
#include <cuda_runtime.h>
#include <cuda_fp16.h>

#define BN   4096
#define LEN  60
#define TS   60
#define HD   256
#define ID   6
#define OD   6
#define GD   1024
#define ROWS 32
#define NTH  1024
#define KDD  264
#define NCTA (BN / ROWS)
#define AST  36          // float stride of activation buffers [k][row]

typedef unsigned long long u64;

// ---------------- device scratch (allocation-free) ----------------
// Gate-interleaved weights: Wg[k][u*4+g] = W_orig[g*256+u][k]  (g: 0=i,1=f,2=g,3=o)
__device__ __align__(16) float g_Wg_e_ih[8 * GD];      // padded to 8 k-rows (6,7 zero)
__device__ __align__(16) float g_Wg_e_hh[HD * GD];
__device__ __align__(16) float g_bg_e[GD];
__device__ __align__(16) float g_Wg_d_ih[KDD * GD];    // k rows 262..263 zero
__device__ __align__(16) float g_Wg_d_hh[HD * GD];
__device__ __align__(16) float g_bg_d[GD];
__device__ __align__(16) float g_l1T[HD * HD];         // [k][u]
__device__ __align__(16) float g_l2T[HD * OD];         // [u][o]
__device__ __align__(16) float g_attnT[262 * 60];      // [k][l]
__device__ __align__(16) __half g_ench[(size_t)BN * LEN * HD];  // encoder outputs fp16

// ---------------- packed fp32x2 helpers ----------------
__device__ __forceinline__ u64 pack2(float v) {
    u64 r; asm("mov.b64 %0, {%1, %1};" : "=l"(r) : "f"(v)); return r;
}
__device__ __forceinline__ u64 pkf2(float a, float b) {
    u64 r; asm("mov.b64 %0, {%1, %2};" : "=l"(r) : "f"(a), "f"(b)); return r;
}
__device__ __forceinline__ u64 fma2(u64 a, u64 b, u64 c) {
    u64 d; asm("fma.rn.f32x2 %0, %1, %2, %3;" : "=l"(d) : "l"(a), "l"(b), "l"(c)); return d;
}
__device__ __forceinline__ float2 unpk(u64 v) {
    float2 f; asm("mov.b64 {%0, %1}, %2;" : "=f"(f.x), "=f"(f.y) : "l"(v)); return f;
}
__device__ __forceinline__ float sigmf(float x) { return 1.0f / (1.0f + __expf(-x)); }

__device__ __forceinline__ unsigned su32(const void* p) {
    unsigned a;
    asm("{ .reg .u64 t; cvta.to.shared.u64 t, %1; cvt.u32.u64 %0, t; }" : "=r"(a) : "l"(p));
    return a;
}
__device__ __forceinline__ void cp16(unsigned d, const void* s) {
    asm volatile("cp.async.cg.shared.global [%0], [%1], 16;" :: "r"(d), "l"(s));
}
__device__ __forceinline__ void cpcommit() { asm volatile("cp.async.commit_group;"); }
__device__ __forceinline__ void cpwait1()  { asm volatile("cp.async.wait_group 1;"); }
__device__ __forceinline__ void cpwait0()  { asm volatile("cp.async.wait_group 0;"); }

// copy one 32KB tile (8192 floats): each of 1024 threads moves 32B
__device__ __forceinline__ void cp_tile(unsigned dst_s, const float* src, int t) {
    unsigned d = dst_s + (unsigned)(t * 32);
    const char* s = (const char*)src + t * 32;
    cp16(d, s); cp16(d + 16, s + 16);
    cpcommit();
}

// main-gemm tile: 8 k-rows; thread owns unit u (cols 4u..4u+3), rows q*8..q*8+7.
__device__ __forceinline__ void tile8(u64 acc[4][4], const float* __restrict__ Ak,
                                      const float* __restrict__ buf, int u, int q) {
#pragma unroll
    for (int kk = 0; kk < 8; kk++) {
        float4 w = *(const float4*)&buf[kk * GD + 4 * u];
        u64 b0 = pack2(w.x), b1 = pack2(w.y), b2 = pack2(w.z), b3 = pack2(w.w);
        const ulonglong2* ap = (const ulonglong2*)(Ak + kk * AST) + q * 2;
        ulonglong2 a01 = ap[0], a23 = ap[1];
        u64 av0 = a01.x, av1 = a01.y, av2 = a23.x, av3 = a23.y;
        acc[0][0] = fma2(av0, b0, acc[0][0]); acc[0][1] = fma2(av0, b1, acc[0][1]);
        acc[0][2] = fma2(av0, b2, acc[0][2]); acc[0][3] = fma2(av0, b3, acc[0][3]);
        acc[1][0] = fma2(av1, b0, acc[1][0]); acc[1][1] = fma2(av1, b1, acc[1][1]);
        acc[1][2] = fma2(av1, b2, acc[1][2]); acc[1][3] = fma2(av1, b3, acc[1][3]);
        acc[2][0] = fma2(av2, b0, acc[2][0]); acc[2][1] = fma2(av2, b1, acc[2][1]);
        acc[2][2] = fma2(av2, b2, acc[2][2]); acc[2][3] = fma2(av2, b3, acc[2][3]);
        acc[3][0] = fma2(av3, b0, acc[3][0]); acc[3][1] = fma2(av3, b1, acc[3][1]);
        acc[3][2] = fma2(av3, b2, acc[3][2]); acc[3][3] = fma2(av3, b3, acc[3][3]);
    }
}

// two-segment pipelined gemm (tiles of 8 k-rows x 1024 cols, triple-buffered)
__device__ __forceinline__ void gemm_pipe(u64 acc[4][4],
        const float* W0, const float* A0, int n0,
        const float* W1, const float* A1, int n1,
        float* wbuf, unsigned wbuf_s, int t, int u, int q) {
    const int NT = n0 + n1;
    cp_tile(wbuf_s, W0, t);
    {
        const float* w1 = (1 < n0) ? (W0 + 8192) : (W1 + (1 - n0) * 8192);
        cp_tile(wbuf_s + 32768, w1, t);
    }
#pragma unroll 1
    for (int j = 0; j < NT; j++) {
        if (j + 1 < NT) cpwait1(); else cpwait0();
        __syncthreads();
        if (j + 2 < NT) {
            int jj = j + 2;
            const float* ws = (jj < n0) ? (W0 + jj * 8192) : (W1 + (jj - n0) * 8192);
            cp_tile(wbuf_s + (unsigned)((jj % 3) * 32768), ws, t);
        }
        const float* Ak = (j < n0) ? (A0 + j * 8 * AST) : (A1 + (j - n0) * 8 * AST);
        tile8(acc, Ak, wbuf + (j % 3) * 8192, u, q);
    }
}

// l1 tile: 32 k-rows x 256 cols; thread (c2 = cols 2c2,2c2+1; rh -> rows rh*4..rh*4+3)
__device__ __forceinline__ void tile32_l1(u64 acc[2][2], const float* __restrict__ Ak,
                                          const float* __restrict__ buf, int c2, int rh) {
#pragma unroll 8
    for (int kk = 0; kk < 32; kk++) {
        float2 w = *(const float2*)&buf[kk * 256 + 2 * c2];
        u64 b0 = pack2(w.x), b1 = pack2(w.y);
        ulonglong2 av = *((const ulonglong2*)(Ak + kk * AST) + rh);
        acc[0][0] = fma2(av.x, b0, acc[0][0]);
        acc[0][1] = fma2(av.x, b1, acc[0][1]);
        acc[1][0] = fma2(av.y, b0, acc[1][0]);
        acc[1][1] = fma2(av.y, b1, acc[1][1]);
    }
}

__device__ __forceinline__ void gemm_pipe_l1(u64 acc[2][2], const float* W0, const float* A0,
                                             float* wbuf, unsigned wbuf_s, int c2, int rh, int t) {
    const int NT = 8;
    cp_tile(wbuf_s, W0, t);
    cp_tile(wbuf_s + 32768, W0 + 8192, t);
#pragma unroll 1
    for (int j = 0; j < NT; j++) {
        if (j + 1 < NT) cpwait1(); else cpwait0();
        __syncthreads();
        if (j + 2 < NT) cp_tile(wbuf_s + (unsigned)(((j + 2) % 3) * 32768), W0 + (j + 2) * 8192, t);
        tile32_l1(acc, A0 + j * 32 * AST, wbuf + (j % 3) * 8192, c2, rh);
    }
}

// ---------------- prep ----------------
__global__ void prep_kernel(const float* __restrict__ eWih, const float* __restrict__ eWhh,
                            const float* __restrict__ ebih, const float* __restrict__ ebhh,
                            const float* __restrict__ aW,
                            const float* __restrict__ dWih, const float* __restrict__ dWhh,
                            const float* __restrict__ dbih, const float* __restrict__ dbhh,
                            const float* __restrict__ l1W, const float* __restrict__ l2W) {
    int tid = blockIdx.x * blockDim.x + threadIdx.x;
    int stride = gridDim.x * blockDim.x;
    for (int i = tid; i < 8 * GD; i += stride) {
        int k = i / GD, cc = i % GD, u = cc >> 2, g = cc & 3;
        g_Wg_e_ih[i] = (k < ID) ? eWih[(g * HD + u) * ID + k] : 0.0f;
    }
    for (int i = tid; i < HD * GD; i += stride) {
        int k = i / GD, cc = i % GD, u = cc >> 2, g = cc & 3;
        g_Wg_e_hh[i] = eWhh[(g * HD + u) * HD + k];
    }
    for (int i = tid; i < GD; i += stride) {
        int u = i >> 2, g = i & 3;
        g_bg_e[i] = ebih[g * HD + u] + ebhh[g * HD + u];
    }
    for (int i = tid; i < KDD * GD; i += stride) {
        int k = i / GD, cc = i % GD, u = cc >> 2, g = cc & 3;
        g_Wg_d_ih[i] = (k < 262) ? dWih[(g * HD + u) * 262 + k] : 0.0f;
    }
    for (int i = tid; i < HD * GD; i += stride) {
        int k = i / GD, cc = i % GD, u = cc >> 2, g = cc & 3;
        g_Wg_d_hh[i] = dWhh[(g * HD + u) * HD + k];
    }
    for (int i = tid; i < GD; i += stride) {
        int u = i >> 2, g = i & 3;
        g_bg_d[i] = dbih[g * HD + u] + dbhh[g * HD + u];
    }
    for (int i = tid; i < HD * HD; i += stride) { int k = i / HD, u = i % HD; g_l1T[i] = l1W[u * HD + k]; }
    for (int i = tid; i < HD * OD; i += stride) { int k = i / OD, o = i % OD; g_l2T[i] = l2W[o * HD + k]; }
    for (int i = tid; i < 262 * 60; i += stride) {
        int k = i / 60, l = i % 60;
        g_attnT[i] = aW[l * 262 + k];
    }
}

// ---------------- main: one CTA owns 32 batch rows end-to-end ----------------
__global__ void __launch_bounds__(NTH, 1) seq_kernel(const float* __restrict__ x,
                                                     const float* __restrict__ attn_b,
                                                     const float* __restrict__ l1b,
                                                     const float* __restrict__ l2b,
                                                     float* __restrict__ out) {
    extern __shared__ float sm[];
    float* Ah    = sm;                    // [256*36]  h (plain f32, [k][row])
    float* Ain   = Ah + 256 * AST;        // [264*36]  dec input
    float* Ax    = Ain + 264 * AST;       // [8*36]    enc x (rows 6,7 zero)
    float* wbuf  = Ax + 8 * AST;          // [3*8192]  cp.async weight tiles
    float* s_s   = wbuf + 3 * 8192;       // [32*60]   scores
    float* z_s   = s_s + 32 * 60;         // [256*33]  l1 output [u][r]
    float* l2T_s = z_s + 256 * 33;        // [256*6]
    float* be_s  = l2T_s + 256 * 6;       // [1024]
    float* bd_s  = be_s + GD;             // [1024]

    const int t  = threadIdx.x;
    const int r0 = blockIdx.x * ROWS;
    const int u  = t & 255;               // unit (gate cols 4u..4u+3)
    const int q  = t >> 8;                // row quarter: rows q*8 .. q*8+7
    const unsigned wbuf_s = su32(wbuf);

    for (int i = t; i < 256 * AST; i += NTH) Ah[i] = 0.0f;
    for (int i = t; i < 8 * AST; i += NTH) Ax[i] = 0.0f;
    for (int i = t; i < GD; i += NTH) { be_s[i] = g_bg_e[i]; bd_s[i] = g_bg_d[i]; }
    if (t < 32) { Ain[262 * AST + t] = 0.0f; Ain[263 * AST + t] = 0.0f; }

    float c[8];
#pragma unroll
    for (int i = 0; i < 8; i++) c[i] = 0.0f;
    __syncthreads();

    // ================= encoder =================
    for (int step = 0; step < LEN; step++) {
        if (t < ROWS * ID) {
            int r = t / ID, k = t - r * ID;
            Ax[k * AST + r] = x[(size_t)(r0 + r) * (LEN * ID) + step * ID + k];
        }
        u64 acc[4][4];
        {
            float4 bv = *(const float4*)&be_s[4 * u];
            u64 q0 = pack2(bv.x), q1 = pack2(bv.y), q2 = pack2(bv.z), q3 = pack2(bv.w);
#pragma unroll
            for (int i = 0; i < 4; i++) { acc[i][0] = q0; acc[i][1] = q1; acc[i][2] = q2; acc[i][3] = q3; }
        }
        gemm_pipe(acc, g_Wg_e_ih, Ax, 1, g_Wg_e_hh, Ah, 32, wbuf, wbuf_s, t, u, q);
        __syncthreads();   // all tile computes read Ah before overwrite

        __half* eb = g_ench + (size_t)r0 * (LEN * HD) + (size_t)step * HD + u;
#pragma unroll
        for (int i = 0; i < 4; i++) {
            float2 gi = unpk(acc[i][0]), gf = unpk(acc[i][1]);
            float2 gg = unpk(acc[i][2]), go = unpk(acc[i][3]);
            float ca = sigmf(gf.x) * c[2 * i]     + sigmf(gi.x) * tanhf(gg.x);
            float cb = sigmf(gf.y) * c[2 * i + 1] + sigmf(gi.y) * tanhf(gg.y);
            float ha = sigmf(go.x) * tanhf(ca);
            float hb = sigmf(go.y) * tanhf(cb);
            c[2 * i] = ca; c[2 * i + 1] = cb;
            int rr = q * 8 + 2 * i;
            *(float2*)&Ah[u * AST + rr] = make_float2(ha, hb);
            eb[(size_t)rr * (LEN * HD)]       = __float2half(ha);
            eb[(size_t)(rr + 1) * (LEN * HD)] = __float2half(hb);
        }
        __syncthreads();
    }

    // ================= decoder init =================
#pragma unroll
    for (int i = 0; i < 8; i++) c[i] = 0.0f;
    for (int i = t; i < 256 * 6; i += NTH) l2T_s[i] = g_l2T[i];
    if (t < 32) {
#pragma unroll
        for (int k = 0; k < OD; k++) Ain[k * AST + t] = (k == 4) ? 1.0f : 0.0f;
    }
    const int lA = t & 63, rgp = t >> 6;   // scores: 16 groups of 2 rows
    const u64 abq = pack2((lA < LEN) ? attn_b[lA] : 0.0f);
    const int c2v = t & 127, rhv = t >> 7; // l1: 2 cols, rows rhv*4..rhv*4+3
    const u64 l1bq0 = pack2(l1b[2 * c2v]), l1bq1 = pack2(l1b[2 * c2v + 1]);
    const int rL2 = t / 6, oL2 = t - 6 * (t / 6);
    const float l2bv = (t < ROWS * OD) ? l2b[oL2] : 0.0f;
    __syncthreads();

    // ================= decoder =================
    for (int step = 0; step < TS; step++) {
        // ---- scores: s[r][l] = [h | tok] . attnT[:, l] + b[l]  (attnT from L2)
        if (lA < LEN) {
            u64 sc0 = abq;
#pragma unroll 8
            for (int k = 0; k < HD; k++) {
                u64 w = pack2(__ldg(&g_attnT[k * 60 + lA]));
                sc0 = fma2(((const u64*)(Ah + k * AST))[rgp], w, sc0);
            }
#pragma unroll
            for (int k = 0; k < OD; k++) {
                u64 w = pack2(__ldg(&g_attnT[(HD + k) * 60 + lA]));
                sc0 = fma2(((const u64*)(Ain + k * AST))[rgp], w, sc0);
            }
            float2 f0 = unpk(sc0);
            s_s[(rgp * 2 + 0) * 60 + lA] = f0.x;
            s_s[(rgp * 2 + 1) * 60 + lA] = f0.y;
        }
        __syncthreads();
        // ---- softmax: warp w handles row w (32 warps, 32 rows)
        {
            int w = t >> 5, lane = t & 31;
            float* sp = &s_s[w * 60];
            float v0 = sp[lane];
            float v1 = (lane + 32 < LEN) ? sp[lane + 32] : -1e30f;
            float m = fmaxf(v0, v1);
#pragma unroll
            for (int d = 16; d > 0; d >>= 1) m = fmaxf(m, __shfl_xor_sync(~0u, m, d));
            float e0 = __expf(v0 - m);
            float e1 = (lane + 32 < LEN) ? __expf(v1 - m) : 0.0f;
            float ss = e0 + e1;
#pragma unroll
            for (int d = 16; d > 0; d >>= 1) ss += __shfl_xor_sync(~0u, ss, d);
            float inv = 1.0f / ss;
            sp[lane] = e0 * inv;
            if (lane + 32 < LEN) sp[lane + 32] = e1 * inv;
        }
        __syncthreads();
        // ---- ctx: thread (r = t>>5, 8 h-cols fp16) -> Ain rows 6..261
        {
            int r = t >> 5, c32 = t & 31;
            u64 a8[4];
#pragma unroll
            for (int j = 0; j < 4; j++) a8[j] = 0ULL;
            const __half* ep = g_ench + (size_t)(r0 + r) * (LEN * HD) + c32 * 8;
            const float* apw = &s_s[r * 60];
#pragma unroll 4
            for (int l = 0; l < LEN; l++) {
                u64 aw = pack2(apw[l]);
                uint4 v0 = *(const uint4*)(ep + (size_t)l * HD);
                const unsigned* vv = &v0.x;
#pragma unroll
                for (int j = 0; j < 4; j++) {
                    float2 f = __half22float2(*(const __half2*)&vv[j]);
                    a8[j] = fma2(aw, pkf2(f.x, f.y), a8[j]);
                }
            }
            int kb = 6 + c32 * 8;
#pragma unroll
            for (int j = 0; j < 4; j++) {
                float2 f = unpk(a8[j]);
                Ain[(kb + 2 * j) * AST + r]     = f.x;
                Ain[(kb + 2 * j + 1) * AST + r] = f.y;
            }
        }
        __syncthreads();

        // ---- decoder gates (pipelined ih K=264 + hh K=256)
        u64 acc[4][4];
        {
            float4 bv = *(const float4*)&bd_s[4 * u];
            u64 q0 = pack2(bv.x), q1 = pack2(bv.y), q2 = pack2(bv.z), q3 = pack2(bv.w);
#pragma unroll
            for (int i = 0; i < 4; i++) { acc[i][0] = q0; acc[i][1] = q1; acc[i][2] = q2; acc[i][3] = q3; }
        }
        gemm_pipe(acc, g_Wg_d_ih, Ain, 33, g_Wg_d_hh, Ah, 32, wbuf, wbuf_s, t, u, q);
        __syncthreads();
#pragma unroll
        for (int i = 0; i < 4; i++) {
            float2 gi = unpk(acc[i][0]), gf = unpk(acc[i][1]);
            float2 gg = unpk(acc[i][2]), go = unpk(acc[i][3]);
            float ca = sigmf(gf.x) * c[2 * i]     + sigmf(gi.x) * tanhf(gg.x);
            float cb = sigmf(gf.y) * c[2 * i + 1] + sigmf(gi.y) * tanhf(gg.y);
            float ha = sigmf(go.x) * tanhf(ca);
            float hb = sigmf(go.y) * tanhf(cb);
            c[2 * i] = ca; c[2 * i + 1] = cb;
            *(float2*)&Ah[u * AST + q * 8 + 2 * i] = make_float2(ha, hb);
        }
        __syncthreads();

        // ---- l1 (pipelined): z = relu(h @ l1T + b1)
        {
            u64 a2[2][2];
            a2[0][0] = l1bq0; a2[0][1] = l1bq1;
            a2[1][0] = l1bq0; a2[1][1] = l1bq1;
            gemm_pipe_l1(a2, g_l1T, Ah, wbuf, wbuf_s, c2v, rhv, t);
#pragma unroll
            for (int i = 0; i < 2; i++) {
                float2 f0 = unpk(a2[i][0]), f1 = unpk(a2[i][1]);
                int rr = rhv * 4 + 2 * i;
                z_s[(2 * c2v) * 33 + rr]     = fmaxf(f0.x, 0.0f);
                z_s[(2 * c2v) * 33 + rr + 1] = fmaxf(f0.y, 0.0f);
                z_s[(2 * c2v + 1) * 33 + rr]     = fmaxf(f1.x, 0.0f);
                z_s[(2 * c2v + 1) * 33 + rr + 1] = fmaxf(f1.y, 0.0f);
            }
        }
        __syncthreads();

        // ---- l2 + output + token feedback
        if (t < ROWS * OD) {
            float s = l2bv;
#pragma unroll 8
            for (int uu = 0; uu < HD; uu++) s += z_s[uu * 33 + rL2] * l2T_s[uu * 6 + oL2];
            out[(size_t)(r0 + rL2) * (TS * OD) + step * OD + oL2] = s;
            Ain[oL2 * AST + rL2] = s;
        }
        __syncthreads();
    }
}

extern "C" void kernel_launch(void* const* d_in, const int* in_sizes, int n_in,
                              void* d_out, int out_size) {
    const float* x    = (const float*)d_in[0];
    const float* eWih = (const float*)d_in[2];
    const float* eWhh = (const float*)d_in[3];
    const float* ebih = (const float*)d_in[4];
    const float* ebhh = (const float*)d_in[5];
    const float* aW   = (const float*)d_in[6];
    const float* ab   = (const float*)d_in[7];
    const float* dWih = (const float*)d_in[8];
    const float* dWhh = (const float*)d_in[9];
    const float* dbih = (const float*)d_in[10];
    const float* dbhh = (const float*)d_in[11];
    const float* l1W  = (const float*)d_in[12];
    const float* l1b  = (const float*)d_in[13];
    const float* l2W  = (const float*)d_in[14];
    const float* l2b  = (const float*)d_in[15];
    float* out = (float*)d_out;

    prep_kernel<<<256, 256>>>(eWih, eWhh, ebih, ebhh, aW, dWih, dWhh, dbih, dbhh, l1W, l2W);

    const int smem_floats = 256 * AST + 264 * AST + 8 * AST + 3 * 8192
                          + 32 * 60 + 256 * 33 + 256 * 6 + 2 * GD;
    const int smem_bytes = smem_floats * (int)sizeof(float);
    cudaFuncSetAttribute(seq_kernel, cudaFuncAttributeMaxDynamicSharedMemorySize, smem_bytes);
    seq_kernel<<<NCTA, NTH, smem_bytes>>>(x, ab, l1b, l2b, out);
}